// round 1
// baseline (speedup 1.0000x reference)
#include <cuda_runtime.h>
#include <cstdint>

// IDWT (Haar, with reference's LH-uses-LPF-twice quirk fused into LL by linearity).
//
// Derivation: out[n,a,b] = 0.5 * ((ll+lh) + sb*hl + sa*sb*hh)
//   sa = (a even ? -1 : +1), sb = (b even ? -1 : +1)
//   (ll,lh,hl,hh) = in[n, a>>1, b>>1, 0..3]   (contiguous float4, channels-last)
//
// Each thread handles TWO adjacent input pixels (r, 2c) and (r, 2c+1):
//   loads  : 2x float4 (contiguous, coalesced)
//   stores : 2x float4 (output cols 4c..4c+3 in rows 2r and 2r+1, coalesced)

namespace {
constexpr int B = 16;
constexpr int H = 512;
constexpr int W = 512;
constexpr int PAIRS_PER_ROW = W / 2;                 // 256
constexpr int TOTAL = B * H * PAIRS_PER_ROW;         // 2,097,152 threads
constexpr int OW = 2 * W;                            // 1024 output width (floats)
}

__global__ void __launch_bounds__(256) idwt_haar_kernel(
    const float4* __restrict__ in, float4* __restrict__ out)
{
    int idx = blockIdx.x * blockDim.x + threadIdx.x;
    if (idx >= TOTAL) return;

    int c = idx & (PAIRS_PER_ROW - 1);       // pair index 0..255
    int r = (idx >> 8) & (H - 1);            // input row 0..511
    int n = idx >> 17;                       // batch 0..15

    const float4* rowp = in + ((size_t)n * H + r) * W;
    float4 p0 = rowp[2 * c];
    float4 p1 = rowp[2 * c + 1];

    // halved components
    float e0  = 0.5f * (p0.x + p0.y);
    float hl0 = 0.5f * p0.z;
    float hh0 = 0.5f * p0.w;
    float e1  = 0.5f * (p1.x + p1.y);
    float hl1 = 0.5f * p1.z;
    float hh1 = 0.5f * p1.w;

    // top row (a = 2r, even -> sa = -1); cols: even b -> sb=-1, odd b -> sb=+1
    float4 top, bot;
    top.x = e0 - hl0 + hh0;   // (2r,   4c  )  b even
    top.y = e0 + hl0 - hh0;   // (2r,   4c+1)  b odd
    top.z = e1 - hl1 + hh1;   // (2r,   4c+2)
    top.w = e1 + hl1 - hh1;   // (2r,   4c+3)
    // bottom row (a = 2r+1, odd -> sa = +1)
    bot.x = e0 - hl0 - hh0;   // (2r+1, 4c  )
    bot.y = e0 + hl0 + hh0;   // (2r+1, 4c+1)
    bot.z = e1 - hl1 - hh1;   // (2r+1, 4c+2)
    bot.w = e1 + hl1 + hh1;   // (2r+1, 4c+3)

    // output float4 index: ((n*1024 + 2r)*1024 + 4c) / 4
    size_t o4 = ((size_t)n * 1024 + 2 * r) * (OW / 4) + c;
    out[o4]            = top;
    out[o4 + OW / 4]   = bot;   // next output row (+1024 floats = +256 float4)
}

extern "C" void kernel_launch(void* const* d_in, const int* in_sizes, int n_in,
                              void* d_out, int out_size)
{
    const float4* in = (const float4*)d_in[0];
    float4* out = (float4*)d_out;
    dim3 block(256);
    dim3 grid((TOTAL + 255) / 256);
    idwt_haar_kernel<<<grid, block>>>(in, out);
}